// round 2
// baseline (speedup 1.0000x reference)
#include <cuda_runtime.h>
#include <cstdint>

// Problem shape
#define BDIM   8192
#define DDIM   2048
#define NUNITS 2048

// GEMM tiling
#define TILE_M 128
#define TILE_N 128
#define KC     128                  // int8 K per stage: 128B rows -> XOR-8 swizzle
#define KITERS (DDIM / KC)          // 16
#define STAGES 3
#define TILE_BYTES (TILE_M * KC)    // 16384 per operand
#define STAGE_BYTES (2 * TILE_BYTES)
#define SMEM_TOTAL (STAGES * STAGE_BYTES)   // 98304

// Scratch (allocation-free rule: __device__ globals)
__device__ __align__(128) int8_t g_A[(size_t)BDIM * DDIM];    // [M, K] K-major
__device__ __align__(128) int8_t g_B[(size_t)NUNITS * DDIM];  // [N, K] K-major (= sign(kernel)^T)

// ============================ PTX helpers ============================

__device__ __forceinline__ uint32_t smem_u32(const void* p) {
    uint32_t a;
    asm("{ .reg .u64 t; cvta.to.shared.u64 t, %1; cvt.u32.u64 %0, t; }" : "=r"(a) : "l"(p));
    return a;
}

__device__ __forceinline__ void cp_async16(uint32_t dst, const void* src) {
    asm volatile("cp.async.cg.shared.global [%0], [%1], 16;" :: "r"(dst), "l"(src) : "memory");
}
#define CP_COMMIT() asm volatile("cp.async.commit_group;" ::: "memory")
#define CP_WAIT(n)  asm volatile("cp.async.wait_group %0;" :: "n"(n) : "memory")

__device__ __forceinline__ void ldm_x4(uint32_t* r, uint32_t addr) {
    asm volatile("ldmatrix.sync.aligned.m8n8.x4.shared.b16 {%0,%1,%2,%3}, [%4];"
                 : "=r"(r[0]), "=r"(r[1]), "=r"(r[2]), "=r"(r[3]) : "r"(addr));
}

__device__ __forceinline__ void mma_s8(int* d, const uint32_t* a, const uint32_t* b) {
    asm volatile(
        "mma.sync.aligned.m16n8k32.row.col.s32.s8.s8.s32 "
        "{%0,%1,%2,%3}, {%4,%5,%6,%7}, {%8,%9}, {%0,%1,%2,%3};"
        : "+r"(d[0]), "+r"(d[1]), "+r"(d[2]), "+r"(d[3])
        : "r"(a[0]), "r"(a[1]), "r"(a[2]), "r"(a[3]), "r"(b[0]), "r"(b[1]));
}

// swizzled byte offset within a [rows][128B] tile for (row r, 16B-chunk c)
__device__ __forceinline__ uint32_t swz(int r, int c) {
    return (uint32_t)(r * 128 + ((c ^ (r & 7)) << 4));
}

// ============================ Convert kernels ============================

// inputs [B, D] fp32 -> g_A [B, D] int8 (+1 / -1). 16 floats -> 16 bytes per thread.
__global__ void sign_a_kernel(const float4* __restrict__ in, int4* __restrict__ out) {
    int i = blockIdx.x * blockDim.x + threadIdx.x;   // one 16-elem group
    const float4* p = in + (size_t)i * 4;
    uint32_t w[4];
#pragma unroll
    for (int j = 0; j < 4; j++) {
        float4 v = p[j];
        uint32_t b0 = (v.x >= 0.f) ? 0x01u : 0xFFu;
        uint32_t b1 = (v.y >= 0.f) ? 0x01u : 0xFFu;
        uint32_t b2 = (v.z >= 0.f) ? 0x01u : 0xFFu;
        uint32_t b3 = (v.w >= 0.f) ? 0x01u : 0xFFu;
        w[j] = b0 | (b1 << 8) | (b2 << 16) | (b3 << 24);
    }
    out[i] = make_int4((int)w[0], (int)w[1], (int)w[2], (int)w[3]);
}

// kernel [D, UNITS] fp32 row-major -> g_B [UNITS, D] int8 (transposed sign)
__global__ void sign_bt_kernel(const float* __restrict__ kern, int8_t* __restrict__ bt) {
    __shared__ int8_t tile[32][36];
    int n0 = blockIdx.x * 32, k0 = blockIdx.y * 32;
    int tx = threadIdx.x, ty = threadIdx.y;           // (32, 8)
#pragma unroll
    for (int j = 0; j < 4; j++) {
        int kk = k0 + ty + j * 8;
        float v = kern[(size_t)kk * NUNITS + n0 + tx];
        tile[ty + j * 8][tx] = (v >= 0.f) ? (int8_t)1 : (int8_t)-1;   // tile[k][n]
    }
    __syncthreads();
    int tid = ty * 32 + tx;
    int nloc = tid >> 3;           // 0..31
    int kgrp = tid & 7;            // 0..7 (4 bytes each)
    uint32_t w = 0;
#pragma unroll
    for (int b = 0; b < 4; b++)
        w |= ((uint32_t)(uint8_t)tile[kgrp * 4 + b][nloc]) << (8 * b);
    *reinterpret_cast<uint32_t*>(bt + (size_t)(n0 + nloc) * DDIM + k0 + kgrp * 4) = w;
}

// ============================ GEMM kernel ============================

__global__ void __launch_bounds__(256, 1) bgemm_imma(
    const int8_t* __restrict__ A, const int8_t* __restrict__ Bt,
    const float* __restrict__ bias, float* __restrict__ out)
{
    extern __shared__ char smem[];
    const uint32_t sb = smem_u32(smem);
    const int tid  = threadIdx.x;
    const int wid  = tid >> 5, lane = tid & 31;
    const int wm   = wid & 3;          // warp M index: 4 x 32 rows
    const int wn   = wid >> 2;         // warp N index: 2 x 64 cols
    const int m0   = blockIdx.y * TILE_M;
    const int n0   = blockIdx.x * TILE_N;

    int acc[2][8][4];
#pragma unroll
    for (int i = 0; i < 2; i++)
#pragma unroll
        for (int j = 0; j < 8; j++)
#pragma unroll
            for (int k = 0; k < 4; k++) acc[i][j][k] = 0;

    // copy-thread coordinates: 1024 16B-chunks per operand tile, 4 per thread
    const int cr = tid >> 3;          // base row (0..31), rows advance by 32 per pass
    const int cc = tid & 7;           // 16B chunk in row

    // ---- pipeline prologue ----
#pragma unroll
    for (int s = 0; s < STAGES - 1; s++) {
        uint32_t sa = sb + s * STAGE_BYTES;
        uint32_t sbuf = sa + TILE_BYTES;
        int ks = s * KC;
#pragma unroll
        for (int p = 0; p < 4; p++) {
            int r = cr + p * 32;
            cp_async16(sa + swz(r, cc),   A  + (size_t)(m0 + r) * DDIM + ks + cc * 16);
            cp_async16(sbuf + swz(r, cc), Bt + (size_t)(n0 + r) * DDIM + ks + cc * 16);
        }
        CP_COMMIT();
    }

    // lane-level ldmatrix coordinates
    const int a_lrow = lane & 15;            // row within 16-row frag
    const int a_csel = lane >> 4;            // 0 = k-lo chunk, 1 = k-hi
    const int b_lrow = (lane & 7) + ((lane >> 4) << 3);  // row within 16-n block
    const int b_csel = (lane >> 3) & 1;

    // ---- mainloop ----
    for (int it = 0; it < KITERS; it++) {
        CP_WAIT(STAGES - 2);
        __syncthreads();

        int s = it % STAGES;
        uint32_t sa = sb + s * STAGE_BYTES;
        uint32_t sbuf = sa + TILE_BYTES;

#pragma unroll
        for (int ks = 0; ks < KC / 32; ks++) {        // 4 k32 steps
            uint32_t afr[2][4];
#pragma unroll
            for (int mf = 0; mf < 2; mf++) {
                int row = wm * 32 + mf * 16 + a_lrow;
                int ch = ks * 2 + a_csel;
                ldm_x4(afr[mf], sa + swz(row, ch));
            }
            uint32_t bfr[8][2];
#pragma unroll
            for (int np = 0; np < 4; np++) {          // 16 n-cols per x4
                int row = wn * 64 + np * 16 + b_lrow;
                int ch = ks * 2 + b_csel;
                uint32_t r4[4];
                ldm_x4(r4, sbuf + swz(row, ch));
                bfr[2 * np][0] = r4[0]; bfr[2 * np][1] = r4[1];
                bfr[2 * np + 1][0] = r4[2]; bfr[2 * np + 1][1] = r4[3];
            }
#pragma unroll
            for (int mf = 0; mf < 2; mf++)
#pragma unroll
                for (int nf = 0; nf < 8; nf++)
                    mma_s8(acc[mf][nf], afr[mf], bfr[nf]);
        }

        __syncthreads();

        int nx = it + STAGES - 1;
        if (nx < KITERS) {
            int sn = nx % STAGES;
            uint32_t na = sb + sn * STAGE_BYTES;
            uint32_t nb = na + TILE_BYTES;
            int ks = nx * KC;
#pragma unroll
            for (int p = 0; p < 4; p++) {
                int r = cr + p * 32;
                cp_async16(na + swz(r, cc), A  + (size_t)(m0 + r) * DDIM + ks + cc * 16);
                cp_async16(nb + swz(r, cc), Bt + (size_t)(n0 + r) * DDIM + ks + cc * 16);
            }
        }
        CP_COMMIT();
    }

    // ---- epilogue: s32 -> f32 + bias, float2 stores ----
    const int row_base = m0 + wm * 32 + (lane >> 2);
    const int col_base = n0 + wn * 64 + 2 * (lane & 3);
#pragma unroll
    for (int nf = 0; nf < 8; nf++) {
        int c = col_base + nf * 8;
        float b0 = bias[c], b1 = bias[c + 1];
#pragma unroll
        for (int mf = 0; mf < 2; mf++) {
            int r = row_base + mf * 16;
            float2 v0 = make_float2((float)acc[mf][nf][0] + b0, (float)acc[mf][nf][1] + b1);
            *reinterpret_cast<float2*>(&out[(size_t)r * NUNITS + c]) = v0;
            float2 v1 = make_float2((float)acc[mf][nf][2] + b0, (float)acc[mf][nf][3] + b1);
            *reinterpret_cast<float2*>(&out[(size_t)(r + 8) * NUNITS + c]) = v1;
        }
    }
}

// ============================ Host ============================

extern "C" void kernel_launch(void* const* d_in, const int* in_sizes, int n_in,
                              void* d_out, int out_size) {
    const float* inputs = (const float*)d_in[0];
    const float* kern   = (const float*)d_in[1];
    const float* bias   = (const float*)d_in[2];
    float* out = (float*)d_out;

    void* pA = nullptr; void* pB = nullptr;
    cudaGetSymbolAddress(&pA, g_A);
    cudaGetSymbolAddress(&pB, g_B);

    // 1) sign-convert A: fp32 -> int8 +-1
    int groups = (BDIM * DDIM) / 16;
    sign_a_kernel<<<groups / 256, 256>>>((const float4*)inputs, (int4*)pA);

    // 2) sign-convert + transpose kernel -> Bt [N, K]
    dim3 tb(32, 8), tg(NUNITS / 32, DDIM / 32);
    sign_bt_kernel<<<tg, tb>>>(kern, (int8_t*)pB);

    // 3) GEMM
    static bool attr_set = false;
    cudaFuncSetAttribute(bgemm_imma, cudaFuncAttributeMaxDynamicSharedMemorySize, SMEM_TOTAL);
    (void)attr_set;
    dim3 grid(NUNITS / TILE_N, BDIM / TILE_M);   // (16, 64)
    bgemm_imma<<<grid, 256, SMEM_TOTAL>>>((const int8_t*)pA, (const int8_t*)pB, bias, out);
}